// round 1
// baseline (speedup 1.0000x reference)
#include <cuda_runtime.h>
#include <math_constants.h>

// CARAFE: features [2,64,64,128] f32 NHWC, masks [2,128,128,25] f32.
// Output [2,128,128,128] f32. k=5, G=1 (Mc=25=k2), Cg=128.
// Nearest 2x upsample index: src = dst/2 (half-pixel centers at exactly 2x).
//
// One block per low-res center (bx, by, b). 4 warps = the 2x2 high-res
// pixels sharing that center's 5x5 window. Each lane = 4 channels (float4).

#define FEAT_H 64
#define FEAT_W 64
#define OUT_H 128
#define OUT_W 128
#define C4 32           // 128 channels / 4
#define K 5
#define K2 25

__global__ __launch_bounds__(128, 8)
void carafe_kernel(const float* __restrict__ feat,
                   const float* __restrict__ masks,
                   float* __restrict__ out)
{
    const int bx = blockIdx.x;   // low-res x: 0..63
    const int by = blockIdx.y;   // low-res y: 0..63
    const int b  = blockIdx.z;   // batch
    const int tid  = threadIdx.x;
    const int wid  = tid >> 5;   // 0..3
    const int lane = tid & 31;

    __shared__ float wsh[4][K2];

    // This warp's high-res output pixel
    const int H = 2 * by + (wid >> 1);
    const int W = 2 * bx + (wid & 1);

    // ---- softmax over the 25 mask logits for (b, H, W) ----
    const float* mp = masks + (((size_t)b * OUT_H + H) * OUT_W + W) * K2;
    float m = (lane < K2) ? mp[lane] : -CUDART_INF_F;

    float mx = m;
    #pragma unroll
    for (int o = 16; o; o >>= 1)
        mx = fmaxf(mx, __shfl_xor_sync(0xffffffffu, mx, o));

    float e = (lane < K2) ? __expf(m - mx) : 0.f;
    float s = e;
    #pragma unroll
    for (int o = 16; o; o >>= 1)
        s += __shfl_xor_sync(0xffffffffu, s, o);

    if (lane < K2) wsh[wid][lane] = e / s;
    __syncwarp();

    // ---- weighted 5x5 window accumulation, 4 channels per lane ----
    const float4* __restrict__ f4 = (const float4*)feat;
    float4 acc = make_float4(0.f, 0.f, 0.f, 0.f);

    #pragma unroll
    for (int di = 0; di < K; di++) {
        const int y = by + di - 2;
        const bool vy = ((unsigned)y < (unsigned)FEAT_H);
        #pragma unroll
        for (int dj = 0; dj < K; dj++) {
            const int x = bx + dj - 2;
            const float wv = wsh[wid][di * K + dj];
            if (vy && ((unsigned)x < (unsigned)FEAT_W)) {
                float4 f = f4[(((size_t)b * FEAT_H + y) * FEAT_W + x) * C4 + lane];
                acc.x = fmaf(wv, f.x, acc.x);
                acc.y = fmaf(wv, f.y, acc.y);
                acc.z = fmaf(wv, f.z, acc.z);
                acc.w = fmaf(wv, f.w, acc.w);
            }
        }
    }

    float4* __restrict__ o4 = (float4*)out;
    o4[(((size_t)b * OUT_H + H) * OUT_W + W) * C4 + lane] = acc;
}

extern "C" void kernel_launch(void* const* d_in, const int* in_sizes, int n_in,
                              void* d_out, int out_size)
{
    const float* feat  = (const float*)d_in[0];   // [2,64,64,128]
    const float* masks = (const float*)d_in[1];   // [2,128,128,25]
    float* out = (float*)d_out;                   // [2,128,128,128]

    dim3 grid(FEAT_W, FEAT_H, 2);
    carafe_kernel<<<grid, 128>>>(feat, masks, out);
}

// round 2
// speedup vs baseline: 1.3589x; 1.3589x over previous
#include <cuda_runtime.h>
#include <math_constants.h>

// CARAFE: features [2,64,64,128] f32 NHWC, masks [2,128,128,25] f32.
// Output [2,128,128,128] f32. k=5, G=1, Cg=128. 2x nearest: src = dst/2.
//
// One WARP per low-res center: computes all 4 high-res output pixels of the
// 2x2 that share this center's 5x5 window. Each tap loaded ONCE (LDG.128 per
// lane = 4 channels), reused in 16 FFMA. Weights for the 4 outputs packed as
// float4 per tap in shared -> single broadcast LDS.128 per tap.

#define FEAT_H 64
#define FEAT_W 64
#define OUT_H 128
#define OUT_W 128
#define C4 32           // 128 channels / 4
#define K 5
#define K2 25
#define WARPS 8         // centers per block

__global__ __launch_bounds__(32 * WARPS, 4)
void carafe_kernel(const float* __restrict__ feat,
                   const float* __restrict__ masks,
                   float* __restrict__ out)
{
    const int tid  = threadIdx.x;
    const int wid  = tid >> 5;
    const int lane = tid & 31;

    // linear center id -> (b, by, bx); consecutive warps = consecutive bx
    const int cid = blockIdx.x * WARPS + wid;
    const int bx = cid & 63;
    const int by = (cid >> 6) & 63;
    const int b  = cid >> 12;

    // weights: [warp][tap] -> float4 (w for the 4 outputs of the 2x2)
    __shared__ float4 wsh[WARPS][K2];

    // ---- 4 softmaxes (one per output pixel of the 2x2) ----
    #pragma unroll
    for (int o = 0; o < 4; o++) {
        const int H = 2 * by + (o >> 1);
        const int W = 2 * bx + (o & 1);
        const float* mp = masks + (((size_t)b * OUT_H + H) * OUT_W + W) * K2;
        float m = (lane < K2) ? mp[lane] : -CUDART_INF_F;

        float mx = m;
        #pragma unroll
        for (int off = 16; off; off >>= 1)
            mx = fmaxf(mx, __shfl_xor_sync(0xffffffffu, mx, off));

        float e = (lane < K2) ? __expf(m - mx) : 0.f;
        float s = e;
        #pragma unroll
        for (int off = 16; off; off >>= 1)
            s += __shfl_xor_sync(0xffffffffu, s, off);

        if (lane < K2) ((float*)&wsh[wid][lane])[o] = e / s;
    }
    __syncwarp();

    // ---- accumulate 5x5 window once into 4 accumulators ----
    const float4* __restrict__ f4 = (const float4*)feat;
    float4 a0 = make_float4(0.f, 0.f, 0.f, 0.f);
    float4 a1 = a0, a2 = a0, a3 = a0;

    #pragma unroll
    for (int di = 0; di < K; di++) {
        const int y = by + di - 2;
        if ((unsigned)y >= (unsigned)FEAT_H) continue;
        #pragma unroll
        for (int dj = 0; dj < K; dj++) {
            const int x = bx + dj - 2;
            if ((unsigned)x >= (unsigned)FEAT_W) continue;
            const float4 f = f4[(((size_t)b * FEAT_H + y) * FEAT_W + x) * C4 + lane];
            const float4 w = wsh[wid][di * K + dj];
            a0.x = fmaf(w.x, f.x, a0.x); a0.y = fmaf(w.x, f.y, a0.y);
            a0.z = fmaf(w.x, f.z, a0.z); a0.w = fmaf(w.x, f.w, a0.w);
            a1.x = fmaf(w.y, f.x, a1.x); a1.y = fmaf(w.y, f.y, a1.y);
            a1.z = fmaf(w.y, f.z, a1.z); a1.w = fmaf(w.y, f.w, a1.w);
            a2.x = fmaf(w.z, f.x, a2.x); a2.y = fmaf(w.z, f.y, a2.y);
            a2.z = fmaf(w.z, f.z, a2.z); a2.w = fmaf(w.z, f.w, a2.w);
            a3.x = fmaf(w.w, f.x, a3.x); a3.y = fmaf(w.w, f.y, a3.y);
            a3.z = fmaf(w.w, f.z, a3.z); a3.w = fmaf(w.w, f.w, a3.w);
        }
    }

    // ---- write the 2x2 outputs ----
    float4* __restrict__ o4 = (float4*)out;
    const int H0 = 2 * by, W0 = 2 * bx;
    o4[(((size_t)b * OUT_H + H0    ) * OUT_W + W0    ) * C4 + lane] = a0;
    o4[(((size_t)b * OUT_H + H0    ) * OUT_W + W0 + 1) * C4 + lane] = a1;
    o4[(((size_t)b * OUT_H + H0 + 1) * OUT_W + W0    ) * C4 + lane] = a2;
    o4[(((size_t)b * OUT_H + H0 + 1) * OUT_W + W0 + 1) * C4 + lane] = a3;
}

extern "C" void kernel_launch(void* const* d_in, const int* in_sizes, int n_in,
                              void* d_out, int out_size)
{
    const float* feat  = (const float*)d_in[0];   // [2,64,64,128]
    const float* masks = (const float*)d_in[1];   // [2,128,128,25]
    float* out = (float*)d_out;                   // [2,128,128,128]

    const int n_centers = 2 * FEAT_H * FEAT_W;    // 8192
    carafe_kernel<<<n_centers / WARPS, 32 * WARPS>>>(feat, masks, out);
}

// round 4
// speedup vs baseline: 1.5435x; 1.1359x over previous
#include <cuda_runtime.h>
#include <math_constants.h>

// CARAFE: features [2,64,64,128] f32 NHWC, masks [2,128,128,25] f32.
// Output [2,128,128,128] f32. k=5, G=1, Cg=128. 2x nearest: src = dst/2.
//
// One WARP per low-res center -> all 4 high-res outputs of its 2x2.
// Branch-free mainloop: out-of-bounds taps get weight 0 (reference
// zero-pads), coordinates clamped so the load is always legal. All 25
// LDG.128 are independent -> ptxas front-batches them (high MLP).

#define FEAT_H 64
#define FEAT_W 64
#define OUT_H 128
#define OUT_W 128
#define C4 32           // 128 channels / 4
#define K 5
#define K2 25
#define WARPS 8         // centers per block

__global__ __launch_bounds__(32 * WARPS, 4)
void carafe_kernel(const float* __restrict__ feat,
                   const float* __restrict__ masks,
                   float* __restrict__ out)
{
    const int tid  = threadIdx.x;
    const int wid  = tid >> 5;
    const int lane = tid & 31;

    const int cid = blockIdx.x * WARPS + wid;
    const int bx = cid & 63;
    const int by = (cid >> 6) & 63;
    const int b  = cid >> 12;

    // weights: [warp][tap] -> float4 (w for the 4 outputs of the 2x2);
    // zeroed for out-of-bounds taps.
    __shared__ float4 wsh[WARPS][K2];

    // tap validity for this center (lane == tap id)
    bool valid = true;
    if (lane < K2) {
        const int di = lane / K, dj = lane % K;
        const int y = by + di - 2, x = bx + dj - 2;
        valid = ((unsigned)y < (unsigned)FEAT_H) & ((unsigned)x < (unsigned)FEAT_W);
    }

    // ---- 4 softmaxes (independent chains; compiler interleaves) ----
    const float* mbase = masks + (((size_t)b * OUT_H + 2 * by) * OUT_W + 2 * bx) * K2;
    #pragma unroll
    for (int o = 0; o < 4; o++) {
        const float* mp = mbase + ((o >> 1) * (size_t)OUT_W + (o & 1)) * K2;
        float m = (lane < K2) ? mp[lane] : -CUDART_INF_F;

        float mx = m;
        #pragma unroll
        for (int off = 16; off; off >>= 1)
            mx = fmaxf(mx, __shfl_xor_sync(0xffffffffu, mx, off));

        float e = (lane < K2) ? __expf(m - mx) : 0.f;
        float s = e;
        #pragma unroll
        for (int off = 16; off; off >>= 1)
            s += __shfl_xor_sync(0xffffffffu, s, off);

        if (lane < K2)
            ((float*)&wsh[wid][lane])[o] = valid ? (e / s) : 0.f;
    }
    __syncwarp();

    // ---- branch-free 5x5 accumulation into 4 accumulators ----
    const float4* __restrict__ f4 = (const float4*)feat;
    const float4* fb = f4 + (size_t)b * FEAT_H * FEAT_W * C4 + lane;

    float4 a0 = make_float4(0.f, 0.f, 0.f, 0.f);
    float4 a1 = a0, a2 = a0, a3 = a0;

    #pragma unroll
    for (int di = 0; di < K; di++) {
        const int y = min(max(by + di - 2, 0), FEAT_H - 1);
        const float4* frow = fb + (size_t)y * FEAT_W * C4;
        #pragma unroll
        for (int dj = 0; dj < K; dj++) {
            const int x = min(max(bx + dj - 2, 0), FEAT_W - 1);
            const float4 f = frow[(size_t)x * C4];
            const float4 w = wsh[wid][di * K + dj];
            a0.x = fmaf(w.x, f.x, a0.x); a0.y = fmaf(w.x, f.y, a0.y);
            a0.z = fmaf(w.x, f.z, a0.z); a0.w = fmaf(w.x, f.w, a0.w);
            a1.x = fmaf(w.y, f.x, a1.x); a1.y = fmaf(w.y, f.y, a1.y);
            a1.z = fmaf(w.y, f.z, a1.z); a1.w = fmaf(w.y, f.w, a1.w);
            a2.x = fmaf(w.z, f.x, a2.x); a2.y = fmaf(w.z, f.y, a2.y);
            a2.z = fmaf(w.z, f.z, a2.z); a2.w = fmaf(w.z, f.w, a2.w);
            a3.x = fmaf(w.w, f.x, a3.x); a3.y = fmaf(w.w, f.y, a3.y);
            a3.z = fmaf(w.w, f.z, a3.z); a3.w = fmaf(w.w, f.w, a3.w);
        }
    }

    // ---- write the 2x2 outputs ----
    float4* __restrict__ o4 = (float4*)out;
    const int H0 = 2 * by, W0 = 2 * bx;
    float4* ob = o4 + (((size_t)b * OUT_H + H0) * OUT_W + W0) * C4 + lane;
    ob[0]                    = a0;
    ob[C4]                   = a1;
    ob[(size_t)OUT_W * C4]        = a2;
    ob[(size_t)OUT_W * C4 + C4]   = a3;
}

extern "C" void kernel_launch(void* const* d_in, const int* in_sizes, int n_in,
                              void* d_out, int out_size)
{
    const float* feat  = (const float*)d_in[0];   // [2,64,64,128]
    const float* masks = (const float*)d_in[1];   // [2,128,128,25]
    float* out = (float*)d_out;                   // [2,128,128,128]

    const int n_centers = 2 * FEAT_H * FEAT_W;    // 8192
    carafe_kernel<<<n_centers / WARPS, 32 * WARPS>>>(feat, masks, out);
}

// round 5
// speedup vs baseline: 1.5702x; 1.0173x over previous
#include <cuda_runtime.h>
#include <math_constants.h>
#include <cstdint>

// CARAFE: features [2,64,64,128] f32 NHWC, masks [2,128,128,25] f32.
// Output [2,128,128,128] f32. k=5, G=1, Cg=128. 2x nearest: src = dst/2.
//
// One WARP per low-res center -> all 4 high-res outputs of its 2x2.
// Mainloop uses packed fp32x2 FMA (fma.rn.f32x2, PTX-only on sm_103a):
//   per tap: 1 ld.global.v2.u64 + 2 ld.shared.v2.u64 + 8 FFMA2
// Weights pre-duplicated as (w,w) pairs in shared so no repack movs.

#define FEAT_H 64
#define FEAT_W 64
#define OUT_H 128
#define OUT_W 128
#define C4 32           // 128 channels / 4
#define K 5
#define K2 25
#define WARPS 8         // centers per block

__global__ __launch_bounds__(32 * WARPS, 4)
void carafe_kernel(const float* __restrict__ feat,
                   const float* __restrict__ masks,
                   float* __restrict__ out)
{
    const int tid  = threadIdx.x;
    const int wid  = tid >> 5;
    const int lane = tid & 31;

    const int cid = blockIdx.x * WARPS + wid;
    const int bx = cid & 63;
    const int by = (cid >> 6) & 63;
    const int b  = cid >> 12;

    // weights duplicated as pairs: [warp][tap][output] = (w, w)
    __shared__ __align__(16) float2 wsh2[WARPS][K2][4];

    // tap validity for this center (lane == tap id); OOB taps -> weight 0
    bool valid = true;
    if (lane < K2) {
        const int di = lane / K, dj = lane % K;
        const int y = by + di - 2, x = bx + dj - 2;
        valid = ((unsigned)y < (unsigned)FEAT_H) & ((unsigned)x < (unsigned)FEAT_W);
    }

    // ---- 4 softmaxes (one per output of the 2x2) ----
    const float* mbase = masks + (((size_t)b * OUT_H + 2 * by) * OUT_W + 2 * bx) * K2;
    #pragma unroll
    for (int o = 0; o < 4; o++) {
        const float* mp = mbase + ((o >> 1) * (size_t)OUT_W + (o & 1)) * K2;
        float m = (lane < K2) ? mp[lane] : -CUDART_INF_F;

        float mx = m;
        #pragma unroll
        for (int off = 16; off; off >>= 1)
            mx = fmaxf(mx, __shfl_xor_sync(0xffffffffu, mx, off));

        float e = (lane < K2) ? __expf(m - mx) : 0.f;
        float s = e;
        #pragma unroll
        for (int off = 16; off; off >>= 1)
            s += __shfl_xor_sync(0xffffffffu, s, off);

        if (lane < K2) {
            const float wv = valid ? (e / s) : 0.f;
            wsh2[wid][lane][o] = make_float2(wv, wv);
        }
    }
    __syncwarp();

    // shared base address (u32) of this warp's weight table
    const uint32_t wbase = (uint32_t)__cvta_generic_to_shared(&wsh2[wid][0][0]);

    // ---- branch-free 5x5 accumulation, packed f32x2 ----
    const float4* __restrict__ f4 = (const float4*)feat;
    const float4* fb = f4 + (size_t)b * FEAT_H * FEAT_W * C4 + lane;

    // 4 outputs x 2 channel-pairs, packed as b64 (two f32 zeros = 0ull)
    uint64_t a00 = 0, a01 = 0, a10 = 0, a11 = 0;
    uint64_t a20 = 0, a21 = 0, a30 = 0, a31 = 0;

    #pragma unroll
    for (int di = 0; di < K; di++) {
        const int y = min(max(by + di - 2, 0), FEAT_H - 1);
        const float4* frow = fb + (size_t)y * FEAT_W * C4;
        #pragma unroll
        for (int dj = 0; dj < K; dj++) {
            const int x = min(max(bx + dj - 2, 0), FEAT_W - 1);
            const float4* fp = frow + (size_t)x * C4;

            uint64_t f0, f1;                      // (c0,c1) (c2,c3)
            asm("ld.global.nc.v2.u64 {%0,%1}, [%2];"
                : "=l"(f0), "=l"(f1) : "l"(fp));

            const uint32_t wa = wbase + (di * K + dj) * 32;
            uint64_t w0, w1, w2, w3;              // (wo,wo) per output
            asm("ld.shared.v2.u64 {%0,%1}, [%2];"
                : "=l"(w0), "=l"(w1) : "r"(wa));
            asm("ld.shared.v2.u64 {%0,%1}, [%2];"
                : "=l"(w2), "=l"(w3) : "r"(wa + 16));

            asm("fma.rn.f32x2 %0, %1, %2, %0;" : "+l"(a00) : "l"(w0), "l"(f0));
            asm("fma.rn.f32x2 %0, %1, %2, %0;" : "+l"(a01) : "l"(w0), "l"(f1));
            asm("fma.rn.f32x2 %0, %1, %2, %0;" : "+l"(a10) : "l"(w1), "l"(f0));
            asm("fma.rn.f32x2 %0, %1, %2, %0;" : "+l"(a11) : "l"(w1), "l"(f1));
            asm("fma.rn.f32x2 %0, %1, %2, %0;" : "+l"(a20) : "l"(w2), "l"(f0));
            asm("fma.rn.f32x2 %0, %1, %2, %0;" : "+l"(a21) : "l"(w2), "l"(f1));
            asm("fma.rn.f32x2 %0, %1, %2, %0;" : "+l"(a30) : "l"(w3), "l"(f0));
            asm("fma.rn.f32x2 %0, %1, %2, %0;" : "+l"(a31) : "l"(w3), "l"(f1));
        }
    }

    // ---- write the 2x2 outputs (packed stores) ----
    float4* __restrict__ o4 = (float4*)out;
    const int H0 = 2 * by, W0 = 2 * bx;
    float4* ob = o4 + (((size_t)b * OUT_H + H0) * OUT_W + W0) * C4 + lane;

    asm volatile("st.global.v2.u64 [%0], {%1,%2};"
                 :: "l"(ob),                          "l"(a00), "l"(a01) : "memory");
    asm volatile("st.global.v2.u64 [%0], {%1,%2};"
                 :: "l"(ob + C4),                     "l"(a10), "l"(a11) : "memory");
    asm volatile("st.global.v2.u64 [%0], {%1,%2};"
                 :: "l"(ob + (size_t)OUT_W * C4),     "l"(a20), "l"(a21) : "memory");
    asm volatile("st.global.v2.u64 [%0], {%1,%2};"
                 :: "l"(ob + (size_t)OUT_W * C4 + C4),"l"(a30), "l"(a31) : "memory");
}

extern "C" void kernel_launch(void* const* d_in, const int* in_sizes, int n_in,
                              void* d_out, int out_size)
{
    const float* feat  = (const float*)d_in[0];   // [2,64,64,128]
    const float* masks = (const float*)d_in[1];   // [2,128,128,25]
    float* out = (float*)d_out;                   // [2,128,128,128]

    const int n_centers = 2 * FEAT_H * FEAT_W;    // 8192
    carafe_kernel<<<n_centers / WARPS, 32 * WARPS>>>(feat, masks, out);
}